// round 2
// baseline (speedup 1.0000x reference)
#include <cuda_runtime.h>
#include <cstdint>

// Problem constants (fixed shapes)
#define Nn 50000
#define Ee 640000
#define Dd 128

// ---------------- device scratch (static; no allocations allowed) --------
__device__ float g_U[Nn * Dd];                    // x @ Wu^T + bu
__device__ float g_B[Nn * Dd];                    // x @ WB^T + bB
__device__ float g_CV[Nn * 2 * Dd];               // per node: [Cx(128) | Vx(128)]
__device__ float g_edge_in[(size_t)Ee * Dd];      // pre-BN edge activations
__device__ float g_agg[Nn * Dd];                  // segment-sum of messages
__device__ float g_stats[1024];                   // [0:128) e_sum [128:256) e_sumsq
                                                  // [256:384) n_sum [384:512) n_sumsq
                                                  // [512..) e_mean,e_rstd,n_mean,n_rstd
__device__ int g_is64;                            // edge_index dtype flag

// ---------------- helpers ------------------------------------------------
__device__ __forceinline__ unsigned long long ffma2(unsigned long long a,
                                                    unsigned long long b,
                                                    unsigned long long c) {
    unsigned long long d;
    asm("fma.rn.f32x2 %0, %1, %2, %3;" : "=l"(d) : "l"(a), "l"(b), "l"(c));
    return d;
}

// Detect int64 vs int32 edge_index: sample 2048 high words; all-zero => int64.
__global__ void detect_kernel(const unsigned* __restrict__ w) {
    __shared__ int sflag;
    if (threadIdx.x == 0) sflag = 0;
    __syncthreads();
    unsigned v = 0;
    for (int i = threadIdx.x; i < 2048; i += blockDim.x) v |= w[2 * i + 1];
    if (v) atomicOr(&sflag, 1);
    __syncthreads();
    if (threadIdx.x == 0) g_is64 = sflag ? 0 : 1;
}

__global__ void zero_kernel() {
    int i = blockIdx.x * blockDim.x + threadIdx.x;
    const int total = Nn * Dd;
    for (int k = i; k < total; k += gridDim.x * blockDim.x) g_agg[k] = 0.f;
    if (i < 1024) g_stats[i] = 0.f;
}

// ---------------- K1: node GEMMs (4 matrices via blockIdx.y) -------------
// Block: 128 threads (one per output feature), 32 nodes per block.
// Weight staged in smem with stride-130 rows; inner loop is packed f32x2 FMA.
__global__ void node_gemm_kernel(const float* __restrict__ x,
                                 const float* __restrict__ Wu, const float* __restrict__ bu,
                                 const float* __restrict__ Wv, const float* __restrict__ bv,
                                 const float* __restrict__ WB, const float* __restrict__ bB,
                                 const float* __restrict__ WC, const float* __restrict__ bC) {
    extern __shared__ float sm[];
    float* ws = sm;                 // 128*130 floats
    float* xs = sm + 128 * 130;     // 32*128 floats
    const int tid = threadIdx.x;
    const int which = blockIdx.y;

    const float* W;
    const float* bias;
    if (which == 0)      { W = Wu; bias = bu; }
    else if (which == 1) { W = Wv; bias = bv; }
    else if (which == 2) { W = WB; bias = bB; }
    else                 { W = WC; bias = bC; }

    const float4* W4 = (const float4*)W;
    for (int i = tid; i < 4096; i += 128) {
        float4 v = W4[i];
        int f = i >> 5;
        int k = (i & 31) << 2;
        float* dst = ws + f * 130 + k;
        dst[0] = v.x; dst[1] = v.y; dst[2] = v.z; dst[3] = v.w;
    }
    const int n0 = blockIdx.x * 32;
    for (int i = tid; i < 32 * 32; i += 128) {
        int n = i >> 5;
        int node = n0 + n;
        float4 v = (node < Nn) ? ((const float4*)x)[(size_t)node * 32 + (i & 31)]
                               : make_float4(0.f, 0.f, 0.f, 0.f);
        *(float4*)(xs + n * 128 + ((i & 31) << 2)) = v;
    }
    __syncthreads();

    const int f = tid;
    unsigned long long acc[32];
#pragma unroll
    for (int n = 0; n < 32; n++) acc[n] = 0ULL;
    const unsigned long long* wrow = (const unsigned long long*)(ws + f * 130);
#pragma unroll 2
    for (int j = 0; j < 64; j++) {
        unsigned long long w2 = wrow[j];
#pragma unroll
        for (int n = 0; n < 32; n++) {
            unsigned long long x2 = *(const unsigned long long*)(xs + n * 128 + 2 * j);
            acc[n] = ffma2(x2, w2, acc[n]);
        }
    }
    float bf = bias[f];
    float* base;
    int rstride, off;
    if (which == 0)      { base = g_U;  rstride = 128; off = 0;   }
    else if (which == 1) { base = g_CV; rstride = 256; off = 128; }
    else if (which == 2) { base = g_B;  rstride = 128; off = 0;   }
    else                 { base = g_CV; rstride = 256; off = 0;   }
#pragma unroll
    for (int n = 0; n < 32; n++) {
        int node = n0 + n;
        if (node < Nn) {
            float lo = __uint_as_float((unsigned)acc[n]);
            float hi = __uint_as_float((unsigned)(acc[n] >> 32));
            base[(size_t)node * rstride + off + f] = lo + hi + bf;
        }
    }
}

// ---------------- K2: edge GEMM + gathers + BN stats (pass 1) ------------
__global__ void edge_gemm_kernel(const float* __restrict__ ea, const void* __restrict__ eidx,
                                 const float* __restrict__ WA, const float* __restrict__ bA) {
    extern __shared__ float sm[];
    float* ws = sm;                         // 128*130
    float* es = sm + 128 * 130;             // 32*128
    int* rows = (int*)(es + 32 * 128);
    int* cols = rows + 32;
    const int tid = threadIdx.x;

    const float4* W4 = (const float4*)WA;
    for (int i = tid; i < 4096; i += 128) {
        float4 v = W4[i];
        int f = i >> 5;
        int k = (i & 31) << 2;
        float* dst = ws + f * 130 + k;
        dst[0] = v.x; dst[1] = v.y; dst[2] = v.z; dst[3] = v.w;
    }
    const int e0 = blockIdx.x * 32;
    const float4* src = (const float4*)(ea + (size_t)e0 * 128);
    float4* dst4 = (float4*)es;
    for (int i = tid; i < 1024; i += 128) dst4[i] = src[i];
    if (tid < 32) {
        long idx = e0 + tid;
        rows[tid] = g_is64 ? (int)((const long long*)eidx)[idx] : ((const int*)eidx)[idx];
    } else if (tid < 64) {
        long idx = (long)Ee + e0 + (tid - 32);
        cols[tid - 32] = g_is64 ? (int)((const long long*)eidx)[idx] : ((const int*)eidx)[idx];
    }
    __syncthreads();

    const int f = tid;
    unsigned long long acc[32];
#pragma unroll
    for (int n = 0; n < 32; n++) acc[n] = 0ULL;
    const unsigned long long* wrow = (const unsigned long long*)(ws + f * 130);
#pragma unroll 2
    for (int j = 0; j < 64; j++) {
        unsigned long long w2 = wrow[j];
#pragma unroll
        for (int n = 0; n < 32; n++) {
            unsigned long long x2 = *(const unsigned long long*)(es + n * 128 + 2 * j);
            acc[n] = ffma2(x2, w2, acc[n]);
        }
    }
    float bf = bA[f];
    float s1 = 0.f, s2 = 0.f;
#pragma unroll 4
    for (int n = 0; n < 32; n++) {
        float lo = __uint_as_float((unsigned)acc[n]);
        float hi = __uint_as_float((unsigned)(acc[n] >> 32));
        float v = lo + hi + bf
                + g_B[(size_t)rows[n] * 128 + f]
                + g_CV[(size_t)cols[n] * 256 + f];
        g_edge_in[(size_t)(e0 + n) * 128 + f] = v;
        s1 += v;
        s2 += v * v;
    }
    atomicAdd(&g_stats[f], s1);
    atomicAdd(&g_stats[128 + f], s2);
}

// ---------------- finalize BN stats (which: 0=edge, 1=node) --------------
__global__ void finalize_kernel(int which, float inv) {
    int f = threadIdx.x;
    float s1 = g_stats[which * 256 + f];
    float s2 = g_stats[which * 256 + 128 + f];
    float mean = s1 * inv;
    float var = fmaxf(s2 * inv - mean * mean, 0.f);
    g_stats[512 + which * 256 + f] = mean;
    g_stats[512 + which * 256 + 128 + f] = rsqrtf(var + 1e-5f);
}

// ---------------- K4: edge pass 2 (BN+relu+residual, messages, segsum) ---
__global__ void edge_pass2_kernel(const float* __restrict__ ea, const void* __restrict__ eidx,
                                  const float* __restrict__ gam, const float* __restrict__ bet,
                                  float* __restrict__ out_e) {
    int e = blockIdx.x * 8 + (threadIdx.x >> 5);
    if (e >= Ee) return;
    int c = (threadIdx.x & 31) * 4;
    int row, col;
    if (g_is64) {
        const long long* p = (const long long*)eidx;
        row = (int)p[e];
        col = (int)p[(size_t)Ee + e];
    } else {
        const int* p = (const int*)eidx;
        row = p[e];
        col = p[Ee + e];
    }
    size_t base = (size_t)e * 128 + c;
    float4 ein = *(const float4*)(g_edge_in + base);
    float4 mu = *(const float4*)(g_stats + 512 + c);
    float4 rs = *(const float4*)(g_stats + 640 + c);
    float4 gm = __ldg((const float4*)(gam + c));
    float4 bt = __ldg((const float4*)(bet + c));
    float4 a4 = __ldg((const float4*)(ea + base));
    float4 eo;
    eo.x = a4.x + fmaxf(gm.x * (ein.x - mu.x) * rs.x + bt.x, 0.f);
    eo.y = a4.y + fmaxf(gm.y * (ein.y - mu.y) * rs.y + bt.y, 0.f);
    eo.z = a4.z + fmaxf(gm.z * (ein.z - mu.z) * rs.z + bt.z, 0.f);
    eo.w = a4.w + fmaxf(gm.w * (ein.w - mu.w) * rs.w + bt.w, 0.f);
    *(float4*)(out_e + base) = eo;

    float4 v4 = *(const float4*)(g_CV + (size_t)col * 256 + 128 + c);
    float mx = v4.x / (1.f + __expf(-eo.x));
    float my = v4.y / (1.f + __expf(-eo.y));
    float mz = v4.z / (1.f + __expf(-eo.z));
    float mw = v4.w / (1.f + __expf(-eo.w));
    float* dst = g_agg + (size_t)row * 128 + c;
    asm volatile("red.global.add.v4.f32 [%0], {%1, %2, %3, %4};"
                 :: "l"(dst), "f"(mx), "f"(my), "f"(mz), "f"(mw) : "memory");
}

// ---------------- K5: node BN stats --------------------------------------
__global__ void node_stats_kernel() {
    int f = threadIdx.x;
    int n0 = blockIdx.x * 64;
    float s1 = 0.f, s2 = 0.f;
    for (int r = 0; r < 64; r++) {
        int n = n0 + r;
        if (n < Nn) {
            float v = g_U[(size_t)n * 128 + f] + g_agg[(size_t)n * 128 + f];
            s1 += v;
            s2 += v * v;
        }
    }
    atomicAdd(&g_stats[256 + f], s1);
    atomicAdd(&g_stats[384 + f], s2);
}

// ---------------- K6: node output ----------------------------------------
__global__ void node_out_kernel(const float* __restrict__ x, const float* __restrict__ gam,
                                const float* __restrict__ bet, float* __restrict__ out_x) {
    int i = blockIdx.x * blockDim.x + threadIdx.x;
    if (i >= Nn * 32) return;
    int c = (i & 31) * 4;
    size_t base = (size_t)i * 4;
    float4 u = *(const float4*)(g_U + base);
    float4 a = *(const float4*)(g_agg + base);
    float4 mu = *(const float4*)(g_stats + 768 + c);
    float4 rs = *(const float4*)(g_stats + 896 + c);
    float4 gm = __ldg((const float4*)(gam + c));
    float4 bt = __ldg((const float4*)(bet + c));
    float4 xv = __ldg((const float4*)(x + base));
    float4 o;
    o.x = xv.x + fmaxf(gm.x * ((u.x + a.x) - mu.x) * rs.x + bt.x, 0.f);
    o.y = xv.y + fmaxf(gm.y * ((u.y + a.y) - mu.y) * rs.y + bt.y, 0.f);
    o.z = xv.z + fmaxf(gm.z * ((u.z + a.z) - mu.z) * rs.z + bt.z, 0.f);
    o.w = xv.w + fmaxf(gm.w * ((u.w + a.w) - mu.w) * rs.w + bt.w, 0.f);
    *(float4*)(out_x + base) = o;
}

// ---------------- launch --------------------------------------------------
extern "C" void kernel_launch(void* const* d_in, const int* in_sizes, int n_in,
                              void* d_out, int out_size) {
    (void)in_sizes; (void)n_in; (void)out_size;
    const float* x  = (const float*)d_in[0];
    const void*  ei = d_in[1];
    const float* ea = (const float*)d_in[2];
    const float* Wu = (const float*)d_in[3];
    const float* bu = (const float*)d_in[4];
    const float* Wv = (const float*)d_in[5];
    const float* bv = (const float*)d_in[6];
    const float* WA = (const float*)d_in[7];
    const float* bA = (const float*)d_in[8];
    const float* WB = (const float*)d_in[9];
    const float* bB = (const float*)d_in[10];
    const float* WC = (const float*)d_in[11];
    const float* bC = (const float*)d_in[12];
    const float* gn_g = (const float*)d_in[13];
    const float* gn_b = (const float*)d_in[14];
    const float* ge_g = (const float*)d_in[15];
    const float* ge_b = (const float*)d_in[16];

    float* out   = (float*)d_out;
    float* out_x = out;
    float* out_e = out + (size_t)Nn * Dd;

    const int smem_node = (128 * 130 + 32 * 128) * 4;          // 82944 B
    const int smem_edge = (128 * 130 + 32 * 128) * 4 + 64 * 4; // 83200 B
    cudaFuncSetAttribute(node_gemm_kernel, cudaFuncAttributeMaxDynamicSharedMemorySize, 86016);
    cudaFuncSetAttribute(edge_gemm_kernel, cudaFuncAttributeMaxDynamicSharedMemorySize, 86016);

    detect_kernel<<<1, 256>>>((const unsigned*)ei);
    zero_kernel<<<2048, 256>>>();
    node_gemm_kernel<<<dim3((Nn + 31) / 32, 4), 128, smem_node>>>(
        x, Wu, bu, Wv, bv, WB, bB, WC, bC);
    edge_gemm_kernel<<<Ee / 32, 128, smem_edge>>>(ea, ei, WA, bA);
    finalize_kernel<<<1, 128>>>(0, 1.0f / (float)Ee);
    edge_pass2_kernel<<<(Ee + 7) / 8, 256>>>(ea, ei, ge_g, ge_b, out_e);
    node_stats_kernel<<<(Nn + 63) / 64, 128>>>();
    finalize_kernel<<<1, 128>>>(1, 1.0f / (float)Nn);
    node_out_kernel<<<(Nn * 32 + 255) / 256, 256>>>(x, gn_g, gn_b, out_x);
}